// round 1
// baseline (speedup 1.0000x reference)
#include <cuda_runtime.h>
#include <math.h>

#define FULLMASK 0xffffffffu

// Problem constants
#define BATCH 2
#define NHEAD 16
#define QLEN  2048
#define KVLEN 4096
#define HDIM  64
#define HID   1024
#define TOPK  32

// ---------------------------------------------------------------------------
// Scratch (device globals: allocation is disallowed)
// ---------------------------------------------------------------------------
__device__ float g_q[(size_t)BATCH * NHEAD * QLEN * HDIM];            // 16 MB
__device__ float g_k[(size_t)BATCH * NHEAD * KVLEN * HDIM];           // 32 MB
__device__ float g_v[(size_t)BATCH * NHEAD * KVLEN * HDIM];           // 32 MB
__device__ float g_attn[(size_t)BATCH * QLEN * HID];                  // 16 MB
__device__ float g_scores[(size_t)BATCH * NHEAD * QLEN * KVLEN];      // 1.07 GB

// ---------------------------------------------------------------------------
// NT GEMM: C[m,n] = scale * sum_k A[m,k]*B[n,k] + bias[n]
// A: [M,K] row-major (lda=K), B: [N,K] row-major (ldb=K)
// mode 0: C[m*N+n]
// mode 1: head-split store: m=(b,mm) with Lper rows/batch, n=(h,d) ->
//         C[((b*NHEAD+h)*Lper+mm)*64 + d]
// Batched via blockIdx.z with strides sA,sB,sC (elements).
// Tile: 128x128, Kstep 16, 256 threads, 8x8 micro-tile (split 4+4).
// ---------------------------------------------------------------------------
__global__ __launch_bounds__(256, 2)
void gemm_nt(const float* __restrict__ A, const float* __restrict__ Bm,
             const float* __restrict__ bias, float* __restrict__ C,
             int M, int N, int K,
             long long sA, long long sB, long long sC,
             float scale, int mode, int Lper)
{
    const int z = blockIdx.z;
    A  += (size_t)z * sA;
    Bm += (size_t)z * sB;
    C  += (size_t)z * sC;

    __shared__ float As[16][132];
    __shared__ float Bs[16][132];

    const int tid = threadIdx.x;
    const int tx = tid & 15;        // 0..15 -> columns
    const int ty = tid >> 4;        // 0..15 -> rows
    const int m0 = blockIdx.y * 128;
    const int n0 = blockIdx.x * 128;

    // load mapping: each thread loads 8 consecutive floats of one row
    const int lrow = tid >> 1;          // 0..127
    const int lcol = (tid & 1) * 8;     // 0 or 8

    float acc[8][8];
#pragma unroll
    for (int i = 0; i < 8; i++)
#pragma unroll
        for (int j = 0; j < 8; j++) acc[i][j] = 0.f;

    const float* agp = A  + (size_t)(m0 + lrow) * K + lcol;
    const float* bgp = Bm + (size_t)(n0 + lrow) * K + lcol;

    for (int k0 = 0; k0 < K; k0 += 16) {
        float4 a0 = *(const float4*)(agp + k0);
        float4 a1 = *(const float4*)(agp + k0 + 4);
        float4 b0 = *(const float4*)(bgp + k0);
        float4 b1 = *(const float4*)(bgp + k0 + 4);

        __syncthreads();   // previous tile fully consumed
        As[lcol + 0][lrow] = a0.x; As[lcol + 1][lrow] = a0.y;
        As[lcol + 2][lrow] = a0.z; As[lcol + 3][lrow] = a0.w;
        As[lcol + 4][lrow] = a1.x; As[lcol + 5][lrow] = a1.y;
        As[lcol + 6][lrow] = a1.z; As[lcol + 7][lrow] = a1.w;
        Bs[lcol + 0][lrow] = b0.x; Bs[lcol + 1][lrow] = b0.y;
        Bs[lcol + 2][lrow] = b0.z; Bs[lcol + 3][lrow] = b0.w;
        Bs[lcol + 4][lrow] = b1.x; Bs[lcol + 5][lrow] = b1.y;
        Bs[lcol + 6][lrow] = b1.z; Bs[lcol + 7][lrow] = b1.w;
        __syncthreads();

#pragma unroll
        for (int kk = 0; kk < 16; kk++) {
            float4 xa0 = *(const float4*)&As[kk][ty * 4];
            float4 xa1 = *(const float4*)&As[kk][64 + ty * 4];
            float4 xb0 = *(const float4*)&Bs[kk][tx * 4];
            float4 xb1 = *(const float4*)&Bs[kk][64 + tx * 4];
            float av[8], bv[8];
            av[0] = xa0.x; av[1] = xa0.y; av[2] = xa0.z; av[3] = xa0.w;
            av[4] = xa1.x; av[5] = xa1.y; av[6] = xa1.z; av[7] = xa1.w;
            bv[0] = xb0.x; bv[1] = xb0.y; bv[2] = xb0.z; bv[3] = xb0.w;
            bv[4] = xb1.x; bv[5] = xb1.y; bv[6] = xb1.z; bv[7] = xb1.w;
#pragma unroll
            for (int i = 0; i < 8; i++)
#pragma unroll
                for (int j = 0; j < 8; j++)
                    acc[i][j] = fmaf(av[i], bv[j], acc[i][j]);
        }
    }

    // epilogue
#pragma unroll
    for (int i = 0; i < 8; i++) {
        const int m = m0 + ((i < 4) ? (ty * 4 + i) : (64 + ty * 4 + (i - 4)));
#pragma unroll
        for (int j = 0; j < 8; j++) {
            const int n = n0 + ((j < 4) ? (tx * 4 + j) : (64 + tx * 4 + (j - 4)));
            float val = acc[i][j] * scale;
            if (bias) val += bias[n];
            if (mode == 0) {
                C[(size_t)m * N + n] = val;
            } else {
                const int bb = m / Lper;
                const int mm = m - bb * Lper;
                const int h = n >> 6;
                const int d = n & 63;
                C[(((size_t)bb * NHEAD + h) * Lper + mm) * 64 + d] = val;
            }
        }
    }
}

// ---------------------------------------------------------------------------
// Warp reductions
// ---------------------------------------------------------------------------
__device__ __forceinline__ float warp_min(float v) {
#pragma unroll
    for (int o = 16; o; o >>= 1) v = fminf(v, __shfl_xor_sync(FULLMASK, v, o));
    return v;
}
__device__ __forceinline__ float warp_max(float v) {
#pragma unroll
    for (int o = 16; o; o >>= 1) v = fmaxf(v, __shfl_xor_sync(FULLMASK, v, o));
    return v;
}
__device__ __forceinline__ float warp_sum(float v) {
#pragma unroll
    for (int o = 16; o; o >>= 1) v += __shfl_xor_sync(FULLMASK, v, o);
    return v;
}

// ---------------------------------------------------------------------------
// Top-32 + softmax + V gather. One warp per (b,h,m) row.
// Row's top-32 list lives in registers: lane l holds (ls, li).
// ---------------------------------------------------------------------------
__global__ __launch_bounds__(256)
void topk_attend(const float* __restrict__ scores, const float* __restrict__ v,
                 float* __restrict__ attn)
{
    const int gwarp = (blockIdx.x * blockDim.x + threadIdx.x) >> 5;
    const int lane = threadIdx.x & 31;
    if (gwarp >= BATCH * NHEAD * QLEN) return;

    const int m = gwarp % QLEN;
    const int h = (gwarp / QLEN) % NHEAD;
    const int b = gwarp / (QLEN * NHEAD);

    const float* srow = scores + (size_t)gwarp * KVLEN;

    float ls = srow[lane];
    int   li = lane;
    float curmin = warp_min(ls);

    for (int c = 1; c < KVLEN / 32; c++) {
        const float s = srow[c * 32 + lane];
        unsigned mask = __ballot_sync(FULLMASK, s > curmin);
        while (mask) {
            const int src = __ffs(mask) - 1;
            mask &= mask - 1;
            const float cs = __shfl_sync(FULLMASK, s, src);
            if (!(cs > curmin)) continue;   // curmin may have risen (uniform)
            // argmin over the 32 list entries
            float mv = ls; int ml = lane;
#pragma unroll
            for (int o = 16; o; o >>= 1) {
                const float ov = __shfl_xor_sync(FULLMASK, mv, o);
                const int   ol = __shfl_xor_sync(FULLMASK, ml, o);
                if (ov < mv || (ov == mv && ol < ml)) { mv = ov; ml = ol; }
            }
            if (lane == ml) { ls = cs; li = c * 32 + src; }
            curmin = warp_min(ls);
        }
    }

    // softmax over the 32 kept scores
    const float mx = warp_max(ls);
    float w = expf(ls - mx);
    const float Z = warp_sum(w);
    w /= Z;

    // gather V rows (head-split layout [B,NH,KV,64]) and accumulate
    const float* vb = v + ((size_t)(b * NHEAD + h)) * KVLEN * HDIM;
    float a0 = 0.f, a1 = 0.f;
#pragma unroll
    for (int e = 0; e < TOPK; e++) {
        const float we = __shfl_sync(FULLMASK, w, e);
        const int   ie = __shfl_sync(FULLMASK, li, e);
        const float* vr = vb + (size_t)ie * HDIM;
        a0 = fmaf(we, vr[lane], a0);
        a1 = fmaf(we, vr[lane + 32], a1);
    }

    float* dst = attn + ((size_t)b * QLEN + m) * HID + h * HDIM;
    dst[lane] = a0;
    dst[lane + 32] = a1;
}

// ---------------------------------------------------------------------------
// Host launcher
// ---------------------------------------------------------------------------
extern "C" void kernel_launch(void* const* d_in, const int* in_sizes, int n_in,
                              void* d_out, int out_size)
{
    const float* query = (const float*)d_in[0];
    const float* key   = (const float*)d_in[1];
    const float* value = (const float*)d_in[2];
    const float* Wq = (const float*)d_in[3];
    const float* bq = (const float*)d_in[4];
    const float* Wk = (const float*)d_in[5];
    const float* bk = (const float*)d_in[6];
    const float* Wv = (const float*)d_in[7];
    const float* bv = (const float*)d_in[8];
    const float* Wo = (const float*)d_in[9];
    const float* bo = (const float*)d_in[10];
    float* out = (float*)d_out;

    float *q, *k, *v, *attn, *sc;
    cudaGetSymbolAddress((void**)&q, g_q);
    cudaGetSymbolAddress((void**)&k, g_k);
    cudaGetSymbolAddress((void**)&v, g_v);
    cudaGetSymbolAddress((void**)&attn, g_attn);
    cudaGetSymbolAddress((void**)&sc, g_scores);

    const dim3 blk(256);

    // Q projection: [4096,1024] @ Wq^T, head-split store into g_q
    gemm_nt<<<dim3(HID / 128, (BATCH * QLEN) / 128, 1), blk>>>(
        query, Wq, bq, q, BATCH * QLEN, HID, HID, 0, 0, 0, 1.f, 1, QLEN);

    // K projection: [8192,1024] @ Wk^T -> g_k
    gemm_nt<<<dim3(HID / 128, (BATCH * KVLEN) / 128, 1), blk>>>(
        key, Wk, bk, k, BATCH * KVLEN, HID, HID, 0, 0, 0, 1.f, 1, KVLEN);

    // V projection -> g_v
    gemm_nt<<<dim3(HID / 128, (BATCH * KVLEN) / 128, 1), blk>>>(
        value, Wv, bv, v, BATCH * KVLEN, HID, HID, 0, 0, 0, 1.f, 1, KVLEN);

    // Scores: per (b,h): [2048,64] @ [4096,64]^T / 8 -> g_scores
    gemm_nt<<<dim3(KVLEN / 128, QLEN / 128, BATCH * NHEAD), blk>>>(
        q, k, nullptr, sc, QLEN, KVLEN, HDIM,
        (long long)QLEN * HDIM, (long long)KVLEN * HDIM, (long long)QLEN * KVLEN,
        0.125f, 0, 0);

    // Top-k + softmax + gather: one warp per row
    topk_attend<<<(BATCH * NHEAD * QLEN) / 8, blk>>>(sc, v, attn);

    // Output projection -> d_out
    gemm_nt<<<dim3(HID / 128, (BATCH * QLEN) / 128, 1), blk>>>(
        attn, Wo, bo, out, BATCH * QLEN, HID, HID, 0, 0, 0, 1.f, 0, 0);
}